// round 9
// baseline (speedup 1.0000x reference)
#include <cuda_runtime.h>
#include <cuda_fp16.h>
#include <math.h>
#include <stdint.h>

#define N_NODES 32767
#define HDIM 256
#define H2 512
#define G4 2048
#define VOCAB 32
#define LEAF0 16383

// ---------------- device state / tables ----------------
__device__ float  g_C[(N_NODES + 1) * HDIM];
__device__ __half g_Hh[(N_NODES + 1) * HDIM];
__device__ float  g_xtabp[VOCAB * G4];          // permuted jj = hid*4+g
__device__ __half g_Wh[G4 * H2];                // permuted rows [jj][k] fp16 (tc path)
__device__ float  g_WhTp[H2 * G4];              // permuted k-major [k][jj] fp32 (small path)
__device__ float  g_ltab_h[VOCAB * H2];
__device__ float  g_ltab_c[VOCAB * HDIM];
__device__ __half g_ltab_h16[VOCAB * HDIM];

__device__ __forceinline__ float tanh_fast(float x) {
    float y;
    asm("tanh.approx.f32 %0, %1;" : "=f"(y) : "f"(x));
    return y;
}
__device__ __forceinline__ float sigm_fast(float x) {
    return fmaf(0.5f, tanh_fast(0.5f * x), 0.5f);
}

__device__ __forceinline__ uint32_t smem_u32(const void* p) {
    uint32_t a;
    asm("{ .reg .u64 t; cvta.to.shared.u64 t, %1; cvt.u32.u64 %0, t; }" : "=r"(a) : "l"(p));
    return a;
}
__device__ __forceinline__ void cpa16(uint32_t dst, const void* src) {
    asm volatile("cp.async.cg.shared.global [%0], [%1], 16;" :: "r"(dst), "l"(src));
}
__device__ __forceinline__ void cp_commit() { asm volatile("cp.async.commit_group;"); }
__device__ __forceinline__ void cp_wait1() { asm volatile("cp.async.wait_group 1;"); }
__device__ __forceinline__ void cp_wait0() { asm volatile("cp.async.wait_group 0;"); }

__device__ __forceinline__ void ldmatrix4(uint32_t& r0, uint32_t& r1, uint32_t& r2, uint32_t& r3,
                                          uint32_t addr) {
    asm volatile("ldmatrix.sync.aligned.m8n8.x4.shared.b16 {%0,%1,%2,%3}, [%4];"
                 : "=r"(r0), "=r"(r1), "=r"(r2), "=r"(r3) : "r"(addr));
}
__device__ __forceinline__ void mma16816(float& d0, float& d1, float& d2, float& d3,
                                         uint32_t a0, uint32_t a1, uint32_t a2, uint32_t a3,
                                         uint32_t b0, uint32_t b1) {
    asm volatile(
        "mma.sync.aligned.m16n8k16.row.col.f32.f16.f16.f32 "
        "{%0,%1,%2,%3}, {%4,%5,%6,%7}, {%8,%9}, {%0,%1,%2,%3};"
        : "+f"(d0), "+f"(d1), "+f"(d2), "+f"(d3)
        : "r"(a0), "r"(a1), "r"(a2), "r"(a3), "r"(b0), "r"(b1));
}

#define SWZ(x) ((x) ^ (((x) >> 3) & 0x70))

// ---------------- tc smem layout ----------------
#define OFF_META   0
#define OFF_STAGE  2048
#define A_BYTES    16384                 // 128 rows x 128B (SW128)
#define B_STRIDE   144                   // 72 fp16/row
#define B_BYTES    (64 * B_STRIDE)       // 9216
#define STAGE_SZ   (A_BYTES + B_BYTES)   // 25600
#define ST_A       0
#define ST_B       A_BYTES
#define SMEM_DYN   (OFF_STAGE + 2 * STAGE_SZ)   // 53248 -> 4 CTAs/SM
#define GST        68

// ---------------- prep: x table (permuted) + leaf tables ----------------
__global__ __launch_bounds__(256) void xtab_kernel(const float* __restrict__ emb,
                                                   const float* __restrict__ W_ih,
                                                   const float* __restrict__ b_ih,
                                                   const float* __restrict__ b_hh) {
    __shared__ float se[256];
    __shared__ float sx[G4];
    int v = blockIdx.x;
    int t = threadIdx.x;
    se[t] = emb[v * 256 + t];
    __syncthreads();
    #pragma unroll
    for (int m = 0; m < 8; m++) {
        int j = m * 256 + t;
        float acc = b_ih[j] + b_hh[j];
        const float4* wr = (const float4*)(W_ih + j * 256);
        #pragma unroll 8
        for (int k4 = 0; k4 < 64; k4++) {
            float4 w = wr[k4];
            acc += w.x * se[k4 * 4 + 0] + w.y * se[k4 * 4 + 1]
                 + w.z * se[k4 * 4 + 2] + w.w * se[k4 * 4 + 3];
        }
        g_xtabp[v * G4 + (j & 511) * 4 + (j >> 9)] = acc;
        sx[j] = acc;
    }
    __syncthreads();
    #pragma unroll
    for (int q = 0; q < 2; q++) {
        int hid = q * 256 + t;
        float ig = sx[hid];
        float gg = sx[1024 + hid];
        float og = sx[1536 + hid];
        float cn = sigm_fast(ig) * tanh_fast(gg);
        float hn = sigm_fast(og) * tanh_fast(cn);
        g_ltab_h[v * H2 + hid] = hn;
        if (q == 0) {
            g_ltab_c[v * HDIM + t] = cn;
            g_ltab_h16[v * HDIM + t] = __float2half_rn(hn);
        }
    }
}

// ---------------- prep: fp16 permuted rows + fp32 permuted k-major ----------------
__global__ void wprep_kernel(const float* __restrict__ W_hh) {
    __shared__ float tile[32][33];
    int j0 = blockIdx.x * 32;
    int k0 = blockIdx.y * 32;
    int tx = threadIdx.x, ty = threadIdx.y;
    #pragma unroll
    for (int r = 0; r < 32; r += 8) {
        int j = j0 + ty + r;
        float w = W_hh[j * H2 + k0 + tx];
        tile[ty + r][tx] = w;
        int jj = (j & 511) * 4 + (j >> 9);
        g_Wh[(size_t)jj * H2 + k0 + tx] = __float2half_rn(w);
    }
    __syncthreads();
    #pragma unroll
    for (int r = 0; r < 32; r += 8) {
        int j = j0 + tx;
        int jj = (j & 511) * 4 + (j >> 9);
        g_WhTp[(size_t)(k0 + ty + r) * G4 + jj] = tile[tx][ty + r];
    }
}

// ---------------- leaves: table copy ----------------
__global__ __launch_bounds__(256) void leaf_kernel(const int* __restrict__ types,
                                                   float* __restrict__ out) {
    int wid = threadIdx.x >> 5;
    int lane = threadIdx.x & 31;
    int node = LEAF0 + blockIdx.x * 8 + wid;
    if (node >= N_NODES) return;
    int v = types[node];
    const float4* sh = (const float4*)(g_ltab_h + (size_t)v * H2);
    float4* dh = (float4*)(out + (size_t)node * H2);
    #pragma unroll
    for (int q = 0; q < 4; q++) dh[lane + 32 * q] = sh[lane + 32 * q];
    const float4* sc = (const float4*)(g_ltab_c + (size_t)v * HDIM);
    float4* dc = (float4*)(g_C + (size_t)node * HDIM);
    #pragma unroll
    for (int q = 0; q < 2; q++) dc[lane + 32 * q] = sc[lane + 32 * q];
    const uint4* s16 = (const uint4*)(g_ltab_h16 + (size_t)v * HDIM);
    uint4* d16 = (uint4*)(g_Hh + (size_t)node * HDIM);
    d16[lane] = s16[lane];
}

// ---------------- HMMA level kernel: M=128 x N=64 x K=512 (levels 13..9) ----------------
__global__ __launch_bounds__(256, 4) void tc_level_kernel(
    const int* __restrict__ types, const int* __restrict__ a_idx,
    const int* __restrict__ b_idx, float* __restrict__ out, int s) {
    extern __shared__ char sp[];
    uint32_t sbase = smem_u32(sp);
    int tid = threadIdx.x;
    int lane = tid & 31;
    int wid = tid >> 5;
    int wm = wid >> 2;
    int wn = wid & 3;
    int by = blockIdx.y;
    int base = s + blockIdx.x * 128;

    int* sa  = (int*)(sp + OFF_META);
    int* sbb = (int*)(sp + OFF_META + 512);
    int* sty = (int*)(sp + OFF_META + 1024);
    if (tid < 128) {
        int i = base + tid;
        sa[tid]  = a_idx[i];
        sbb[tid] = b_idx[i];
        sty[tid] = types[i];
    }
    __syncthreads();

    int arow = tid >> 1, ahalf = tid & 1;
    int brow = tid >> 2, bq = tid & 3;

    auto load_chunk = [&](int kc, int st) {
        uint32_t stg = sbase + OFF_STAGE + st * STAGE_SZ;
        int child = (kc < 4) ? sa[arow] : sbb[arow];
        int col0 = (kc & 3) * 64 + ahalf * 32;
        const char* ah = (const char*)(g_Hh + (size_t)child * HDIM + col0);
        #pragma unroll
        for (int q = 0; q < 4; q++) {
            uint32_t boff = arow * 128 + ahalf * 64 + q * 16;
            cpa16(stg + ST_A + SWZ(boff), ah + q * 16);
        }
        const char* wh = (const char*)(g_Wh + (size_t)(by * 64 + brow) * H2 + kc * 64) + bq * 32;
        cpa16(stg + ST_B + brow * B_STRIDE + bq * 32, wh);
        cpa16(stg + ST_B + brow * B_STRIDE + bq * 32 + 16, wh + 16);
        cp_commit();
    };

    float acc[4][2][4];
    #pragma unroll
    for (int mt = 0; mt < 4; mt++)
        #pragma unroll
        for (int nb = 0; nb < 2; nb++)
            #pragma unroll
            for (int r = 0; r < 4; r++) acc[mt][nb][r] = 0.0f;

    load_chunk(0, 0);

    for (int kc = 0; kc < 8; kc++) {
        if (kc < 7) load_chunk(kc + 1, (kc + 1) & 1);
        if (kc < 7) cp_wait1(); else cp_wait0();
        __syncthreads();

        uint32_t stg = sbase + OFF_STAGE + (kc & 1) * STAGE_SZ;

        #pragma unroll
        for (int ks = 0; ks < 4; ks++) {
            int k0 = ks * 16;
            uint32_t bf[2][2];
            int sel = lane >> 3;
            int rinm = lane & 7;
            {
                int n = wn * 16 + (sel >> 1) * 8 + rinm;
                uint32_t bptr = stg + ST_B + n * B_STRIDE + k0 * 2 + (sel & 1) * 16;
                ldmatrix4(bf[0][0], bf[0][1], bf[1][0], bf[1][1], bptr);
            }
            #pragma unroll
            for (int mt = 0; mt < 4; mt++) {
                int row = wm * 64 + mt * 16 + (lane & 15);
                uint32_t boff = SWZ((uint32_t)(row * 128 + k0 * 2 + (lane >> 4) * 16));
                uint32_t a0, a1, a2, a3;
                ldmatrix4(a0, a1, a2, a3, stg + ST_A + boff);
                #pragma unroll
                for (int nb = 0; nb < 2; nb++)
                    mma16816(acc[mt][nb][0], acc[mt][nb][1], acc[mt][nb][2], acc[mt][nb][3],
                             a0, a1, a2, a3, bf[nb][0], bf[nb][1]);
            }
        }
        __syncthreads();
    }

    float* gates = (float*)(sp + OFF_STAGE);
    #pragma unroll
    for (int mt = 0; mt < 4; mt++) {
        #pragma unroll
        for (int nb = 0; nb < 2; nb++) {
            int r0 = wm * 64 + mt * 16 + (lane >> 2);
            int c0 = wn * 16 + nb * 8 + ((lane & 3) << 1);
            gates[r0 * GST + c0]           = acc[mt][nb][0];
            gates[r0 * GST + c0 + 1]       = acc[mt][nb][1];
            gates[(r0 + 8) * GST + c0]     = acc[mt][nb][2];
            gates[(r0 + 8) * GST + c0 + 1] = acc[mt][nb][3];
        }
    }
    __syncthreads();

    int hl = tid & 15;
    int hid_g = by * 16 + hl;
    #pragma unroll 4
    for (int it = 0; it < 8; it++) {
        int m = (tid >> 4) + (it << 4);
        int node = base + m;
        int child = (by < 16) ? sa[m] : sbb[m];
        float4 gt = *(const float4*)(gates + m * GST + hl * 4);
        float4 xt = *(const float4*)(g_xtabp + (size_t)sty[m] * G4 + by * 64 + hl * 4);
        float ig = gt.x + xt.x;
        float fg = gt.y + xt.y;
        float gg = gt.z + xt.z;
        float og = gt.w + xt.w;
        float co = g_C[(size_t)child * HDIM + (hid_g & 255)];
        float cn = sigm_fast(fg) * co + sigm_fast(ig) * tanh_fast(gg);
        float hn = sigm_fast(og) * tanh_fast(cn);
        out[(size_t)node * H2 + hid_g] = hn;
        if (by < 16) {
            g_C[(size_t)node * HDIM + hid_g] = cn;
            g_Hh[(size_t)node * HDIM + hid_g] = __float2half_rn(hn);
        }
    }
}

// ---------------- fused small-level kernel: 8 nodes x 256 jj per CTA (levels 8..0) ----------------
__global__ __launch_bounds__(256) void fused_level_kernel(
    const int* __restrict__ types, const int* __restrict__ a_idx,
    const int* __restrict__ b_idx, float* __restrict__ out, int s, int n) {
    __shared__ float hbuf[8][H2];
    __shared__ float sgates[8][256];
    __shared__ int sa[8], sb[8], sty[8];
    int t = threadIdx.x;
    int base = s + blockIdx.x * 8;
    int c0 = blockIdx.y * 256;                 // jj slice
    if (t < 8) {
        int i = base + t;
        int v = (i < s + n);
        sa[t] = v ? a_idx[i] : N_NODES;
        sb[t] = v ? b_idx[i] : N_NODES;
        sty[t] = v ? types[i] : 0;
    }
    __syncthreads();
    #pragma unroll
    for (int q = 0; q < 16; q++) {
        int idx = q * 256 + t;
        int r = idx >> 9, k = idx & 511;
        int child = (k < HDIM) ? sa[r] : sb[r];
        hbuf[r][k] = __half2float(g_Hh[(size_t)child * HDIM + (k & 255)]);
    }
    __syncthreads();

    int jj = c0 + t;
    float acc[8];
    #pragma unroll
    for (int r = 0; r < 8; r++) acc[r] = g_xtabp[(size_t)sty[r] * G4 + jj];
    const float* wp = g_WhTp + jj;
    #pragma unroll 2
    for (int k4 = 0; k4 < 128; k4++) {
        float w0 = wp[(size_t)(k4 * 4 + 0) * G4];
        float w1 = wp[(size_t)(k4 * 4 + 1) * G4];
        float w2 = wp[(size_t)(k4 * 4 + 2) * G4];
        float w3 = wp[(size_t)(k4 * 4 + 3) * G4];
        #pragma unroll
        for (int r = 0; r < 8; r++) {
            float4 h4 = *(const float4*)&hbuf[r][k4 * 4];
            acc[r] = fmaf(w0, h4.x, acc[r]);
            acc[r] = fmaf(w1, h4.y, acc[r]);
            acc[r] = fmaf(w2, h4.z, acc[r]);
            acc[r] = fmaf(w3, h4.w, acc[r]);
        }
    }
    #pragma unroll
    for (int r = 0; r < 8; r++) sgates[r][t] = acc[r];
    __syncthreads();

    // epilogue: 8 nodes x 64 hids for this slice
    #pragma unroll
    for (int q = 0; q < 2; q++) {
        int o = q * 256 + t;
        int r = o >> 6;
        int hid_l = o & 63;
        int node = base + r;
        if (node < s + n) {
            int hid_g = blockIdx.y * 64 + hid_l;
            float ig = sgates[r][hid_l * 4 + 0];
            float fg = sgates[r][hid_l * 4 + 1];
            float gg = sgates[r][hid_l * 4 + 2];
            float og = sgates[r][hid_l * 4 + 3];
            int child = (hid_g < HDIM) ? sa[r] : sb[r];
            float co = g_C[(size_t)child * HDIM + (hid_g & 255)];
            float cn = sigm_fast(fg) * co + sigm_fast(ig) * tanh_fast(gg);
            float hn = sigm_fast(og) * tanh_fast(cn);
            out[(size_t)node * H2 + hid_g] = hn;
            if (hid_g < HDIM) {
                g_C[(size_t)node * HDIM + hid_g] = cn;
                g_Hh[(size_t)node * HDIM + hid_g] = __float2half_rn(hn);
            }
        }
    }
}

extern "C" void kernel_launch(void* const* d_in, const int* in_sizes, int n_in,
                              void* d_out, int out_size) {
    const int* types  = (const int*)d_in[0];
    const int* a_idx  = (const int*)d_in[1];
    const int* b_idx  = (const int*)d_in[2];
    const float* emb  = (const float*)d_in[3];
    const float* W_ih = (const float*)d_in[4];
    const float* W_hh = (const float*)d_in[5];
    const float* b_ih = (const float*)d_in[6];
    const float* b_hh = (const float*)d_in[7];
    float* out = (float*)d_out;

    cudaFuncSetAttribute(tc_level_kernel, cudaFuncAttributeMaxDynamicSharedMemorySize, SMEM_DYN);

    // #1..#3 prep + leaves; #4 = tc13 (profiled)
    xtab_kernel<<<VOCAB, 256>>>(emb, W_ih, b_ih, b_hh);
    wprep_kernel<<<dim3(G4 / 32, H2 / 32), dim3(32, 8)>>>(W_hh);
    leaf_kernel<<<2048, 256>>>(types, out);

    for (int d = 13; d >= 9; d--) {
        int n = 1 << d;
        int s = n - 1;
        tc_level_kernel<<<dim3(n / 128, 32), 256, SMEM_DYN>>>(types, a_idx, b_idx, out, s);
    }
    for (int d = 8; d >= 0; d--) {
        int n = 1 << d;
        int s = n - 1;
        fused_level_kernel<<<dim3((n + 7) / 8, 8), 256>>>(types, a_idx, b_idx, out, s, n);
    }
}